// round 1
// baseline (speedup 1.0000x reference)
#include <cuda_runtime.h>
#include <math.h>

// Problem constants
#define NEMBD 1024
#define NHEAD 16
#define HDIM  64
#define TSEQ  2048
#define BATCH 4

// Scratch buffers as device globals (allocation inside kernel_launch is forbidden).
__device__ float g_qkv[(size_t)BATCH * TSEQ * 3 * NEMBD]; // [B,T,3C]
__device__ float g_y[(size_t)BATCH * TSEQ * NEMBD];       // [B,T,C]

// ---------------------------------------------------------------------------
// SGEMM: C[M,N] = A[M,K] @ B[K,N], all row-major, fp32.
// 128x128 block tile, BK=16, 8x8 per-thread tile, 256 threads.
// Dims must be multiples of the tile sizes (they are: 8192/3072/1024/1024).
// ---------------------------------------------------------------------------
template<int BM, int BN, int BK, int TM, int TN>
__global__ __launch_bounds__((BM / TM) * (BN / TN))
void sgemm_kernel(const float* __restrict__ A, const float* __restrict__ B,
                  float* __restrict__ C, int M, int N, int K)
{
    __shared__ __align__(16) float As[BK][BM]; // transposed A tile
    __shared__ __align__(16) float Bs[BK][BN];

    constexpr int NT = (BM / TM) * (BN / TN);
    const int tid = threadIdx.x;
    const int tx = tid % (BN / TN);
    const int ty = tid / (BN / TN);
    const int rowBase = blockIdx.y * BM;
    const int colBase = blockIdx.x * BN;

    float acc[TM][TN];
#pragma unroll
    for (int m = 0; m < TM; ++m)
#pragma unroll
        for (int n = 0; n < TN; ++n) acc[m][n] = 0.0f;

    float ra[TM], rb[TN];

    for (int k0 = 0; k0 < K; k0 += BK) {
        // Load A tile (BM x BK) into As transposed: As[k][m]
#pragma unroll
        for (int i = 0; i < (BM * BK / 4) / NT; ++i) {
            int v = tid + i * NT;
            int ar = v / (BK / 4);
            int ac4 = v % (BK / 4);
            float4 t = *(const float4*)(A + (size_t)(rowBase + ar) * K + k0 + ac4 * 4);
            As[ac4 * 4 + 0][ar] = t.x;
            As[ac4 * 4 + 1][ar] = t.y;
            As[ac4 * 4 + 2][ar] = t.z;
            As[ac4 * 4 + 3][ar] = t.w;
        }
        // Load B tile (BK x BN)
#pragma unroll
        for (int i = 0; i < (BK * BN / 4) / NT; ++i) {
            int v = tid + i * NT;
            int br = v / (BN / 4);
            int bc4 = v % (BN / 4);
            *(float4*)(&Bs[br][bc4 * 4]) =
                *(const float4*)(B + (size_t)(k0 + br) * N + colBase + bc4 * 4);
        }
        __syncthreads();

#pragma unroll
        for (int k = 0; k < BK; ++k) {
#pragma unroll
            for (int m = 0; m < TM; m += 4)
                *(float4*)&ra[m] = *(const float4*)(&As[k][ty * TM + m]);
#pragma unroll
            for (int n = 0; n < TN; n += 4)
                *(float4*)&rb[n] = *(const float4*)(&Bs[k][tx * TN + n]);
#pragma unroll
            for (int m = 0; m < TM; ++m)
#pragma unroll
                for (int n = 0; n < TN; ++n)
                    acc[m][n] += ra[m] * rb[n];
        }
        __syncthreads();
    }

#pragma unroll
    for (int m = 0; m < TM; ++m) {
        float* cp = C + (size_t)(rowBase + ty * TM + m) * N + colBase + tx * TN;
#pragma unroll
        for (int n = 0; n < TN; n += 4) {
            float4 t = make_float4(acc[m][n], acc[m][n + 1], acc[m][n + 2], acc[m][n + 3]);
            *(float4*)(cp + n) = t;
        }
    }
}

// ---------------------------------------------------------------------------
// Causal flash attention, fp32.
// One thread owns one query row (q, o, m, l in registers).
// K/V blocks of 64 staged in smem; inner reads are warp-uniform (broadcast).
// Online softmax with rescale-only-on-new-max (expected ~ln(T) rescales/row).
// Grid: (T/BQ, B*H), 128 threads.
// ---------------------------------------------------------------------------
#define BQ  128
#define BKV 64

__global__ __launch_bounds__(128)
void attn_kernel(const float* __restrict__ qkv, float* __restrict__ y)
{
    const int qb  = blockIdx.x;
    const int bh  = blockIdx.y;
    const int b   = bh / NHEAD;
    const int h   = bh % NHEAD;
    const int tid = threadIdx.x;
    const int qi  = qb * BQ + tid; // query index in [0, TSEQ)

    const int C3 = 3 * NEMBD;
    const float* base = qkv + (size_t)b * TSEQ * C3;

    // Load q row (pre-scaled by 1/sqrt(D))
    const float* qptr = base + (size_t)qi * C3 + h * HDIM;
    float qreg[HDIM];
#pragma unroll
    for (int d = 0; d < HDIM; d += 4) {
        float4 t = *(const float4*)(qptr + d);
        qreg[d + 0] = t.x * 0.125f;
        qreg[d + 1] = t.y * 0.125f;
        qreg[d + 2] = t.z * 0.125f;
        qreg[d + 3] = t.w * 0.125f;
    }

    float o[HDIM];
#pragma unroll
    for (int d = 0; d < HDIM; ++d) o[d] = 0.0f;
    float mrow = -INFINITY;
    float lrow = 0.0f;

    __shared__ __align__(16) float Ks[BKV][HDIM];
    __shared__ __align__(16) float Vs[BKV][HDIM];

    const int nkb = (qb * BQ + BQ - 1) / BKV + 1; // key blocks covering this q block

    for (int kb = 0; kb < nkb; ++kb) {
        __syncthreads(); // previous block's compute done before overwrite
        const float* kbase = base + (size_t)(kb * BKV) * C3 + NEMBD + h * HDIM;
        const float* vbase = base + (size_t)(kb * BKV) * C3 + 2 * NEMBD + h * HDIM;
#pragma unroll
        for (int i = 0; i < (BKV * HDIM / 4) / 128; ++i) { // 8 float4s per thread per tile
            int idx = tid + i * 128;
            int row = idx / (HDIM / 4);
            int c4  = idx % (HDIM / 4);
            *(float4*)(&Ks[row][c4 * 4]) = *(const float4*)(kbase + (size_t)row * C3 + c4 * 4);
            *(float4*)(&Vs[row][c4 * 4]) = *(const float4*)(vbase + (size_t)row * C3 + c4 * 4);
        }
        __syncthreads();

        const int jmax = min(BKV, qi - kb * BKV + 1); // #valid (causal) keys in block
        for (int j = 0; j < jmax; ++j) {
            float s = 0.0f;
#pragma unroll
            for (int d = 0; d < HDIM; d += 4) {
                float4 k4 = *(const float4*)(&Ks[j][d]);
                s += qreg[d + 0] * k4.x + qreg[d + 1] * k4.y
                   + qreg[d + 2] * k4.z + qreg[d + 3] * k4.w;
            }
            if (s > mrow) {
                float alpha = __expf(mrow - s); // 0 on first hit (mrow = -inf)
                lrow *= alpha;
#pragma unroll
                for (int d = 0; d < HDIM; ++d) o[d] *= alpha;
                mrow = s;
            }
            float p = __expf(s - mrow);
            lrow += p;
#pragma unroll
            for (int d = 0; d < HDIM; d += 4) {
                float4 v4 = *(const float4*)(&Vs[j][d]);
                o[d + 0] += p * v4.x;
                o[d + 1] += p * v4.y;
                o[d + 2] += p * v4.z;
                o[d + 3] += p * v4.w;
            }
        }
    }

    const float inv_l = 1.0f / lrow;
    float* yptr = y + (size_t)(b * TSEQ + qi) * NEMBD + h * HDIM;
#pragma unroll
    for (int d = 0; d < HDIM; d += 4) {
        float4 t = make_float4(o[d] * inv_l, o[d + 1] * inv_l,
                               o[d + 2] * inv_l, o[d + 3] * inv_l);
        *(float4*)(yptr + d) = t;
    }
}

// ---------------------------------------------------------------------------
// Launch
// ---------------------------------------------------------------------------
extern "C" void kernel_launch(void* const* d_in, const int* in_sizes, int n_in,
                              void* d_out, int out_size)
{
    const float* x      = (const float*)d_in[0]; // [4,2048,1024]
    const float* w_attn = (const float*)d_in[1]; // [1024,3072]
    const float* w_proj = (const float*)d_in[2]; // [1024,1024]
    float* out = (float*)d_out;                  // [4,2048,1024]

    float* qkv = nullptr;
    float* y   = nullptr;
    cudaGetSymbolAddress((void**)&qkv, g_qkv);
    cudaGetSymbolAddress((void**)&y, g_y);

    const int M = BATCH * TSEQ;   // 8192
    const int K = NEMBD;          // 1024
    const int N1 = 3 * NEMBD;     // 3072
    const int N2 = NEMBD;         // 1024

    // Stage 1: qkv = x @ w_attn
    {
        dim3 grid(N1 / 128, M / 128);
        sgemm_kernel<128, 128, 16, 8, 8><<<grid, 256>>>(x, w_attn, qkv, M, N1, K);
    }
    // Stage 2: flash attention -> y
    {
        dim3 grid(TSEQ / BQ, BATCH * NHEAD);
        attn_kernel<<<grid, 128>>>(qkv, y);
    }
    // Stage 3: out = y @ w_proj
    {
        dim3 grid(N2 / 128, M / 128);
        sgemm_kernel<128, 128, 16, 8, 8><<<grid, 256>>>(y, w_proj, out, M, N2, K);
    }
}

// round 3
// speedup vs baseline: 1.3878x; 1.3878x over previous
#include <cuda_runtime.h>
#include <cuda_bf16.h>
#include <math.h>
#include <stdint.h>

// Problem constants
#define NEMBD 1024
#define NHEAD 16
#define HDIM  64
#define TSEQ  2048
#define BATCH 4

// ---------------------------------------------------------------------------
// Scratch (device globals; allocation in kernel_launch is forbidden)
// ---------------------------------------------------------------------------
__device__ float g_qkv[(size_t)BATCH * TSEQ * 3 * NEMBD]; // [B,T,3C] fp32
__device__ float g_y[(size_t)BATCH * TSEQ * NEMBD];       // [B,T,C]  fp32
__device__ __nv_bfloat16 g_a_hi[(size_t)BATCH * TSEQ * NEMBD]; // A split (x, later y)
__device__ __nv_bfloat16 g_a_lo[(size_t)BATCH * TSEQ * NEMBD];
__device__ __nv_bfloat16 g_wq_hi[(size_t)3 * NEMBD * NEMBD];   // w_attn^T [3072][1024]
__device__ __nv_bfloat16 g_wq_lo[(size_t)3 * NEMBD * NEMBD];
__device__ __nv_bfloat16 g_wp_hi[(size_t)NEMBD * NEMBD];       // w_proj^T [1024][1024]
__device__ __nv_bfloat16 g_wp_lo[(size_t)NEMBD * NEMBD];

// ---------------------------------------------------------------------------
// PTX helpers (base ISA only — no tcgen05; harness targets sm_103 w/o 'a')
// ---------------------------------------------------------------------------
__device__ __forceinline__ uint32_t smem_u32(const void* p) {
    uint32_t a;
    asm("{ .reg .u64 t; cvta.to.shared.u64 t, %1; cvt.u32.u64 %0, t; }" : "=r"(a) : "l"(p));
    return a;
}
#define CP_ASYNC16(sm, gm) \
    asm volatile("cp.async.cg.shared.global [%0], [%1], 16;" :: "r"(sm), "l"(gm))
#define CP_COMMIT() asm volatile("cp.async.commit_group;" ::: "memory")
#define CP_WAIT(n)  asm volatile("cp.async.wait_group %0;" :: "n"(n) : "memory")

__device__ __forceinline__ void mma16816(float* c, const uint32_t* a, const uint32_t* b) {
    asm volatile(
        "mma.sync.aligned.m16n8k16.row.col.f32.bf16.bf16.f32 "
        "{%0,%1,%2,%3}, {%4,%5,%6,%7}, {%8,%9}, {%0,%1,%2,%3};"
        : "+f"(c[0]), "+f"(c[1]), "+f"(c[2]), "+f"(c[3])
        : "r"(a[0]), "r"(a[1]), "r"(a[2]), "r"(a[3]), "r"(b[0]), "r"(b[1]));
}

// ---------------------------------------------------------------------------
// Conversion kernels
// ---------------------------------------------------------------------------
__global__ __launch_bounds__(256)
void split_kernel(const float* __restrict__ in, __nv_bfloat16* __restrict__ hi,
                  __nv_bfloat16* __restrict__ lo, int n4)
{
    int idx = blockIdx.x * blockDim.x + threadIdx.x;
    if (idx >= n4) return;
    float4 v = ((const float4*)in)[idx];
    __nv_bfloat16 h[4], l[4];
    float f[4] = {v.x, v.y, v.z, v.w};
#pragma unroll
    for (int i = 0; i < 4; ++i) {
        h[i] = __float2bfloat16_rn(f[i]);
        l[i] = __float2bfloat16_rn(f[i] - __bfloat162float(h[i]));
    }
    ((uint2*)hi)[idx] = *(const uint2*)h;
    ((uint2*)lo)[idx] = *(const uint2*)l;
}

// w [K][N] fp32 -> hi/lo bf16 [N][K] (transposed). Block (32,8), grid (N/32, K/32).
__global__ __launch_bounds__(256)
void tsplit_kernel(const float* __restrict__ w, __nv_bfloat16* __restrict__ hi,
                   __nv_bfloat16* __restrict__ lo, int K, int N)
{
    __shared__ float t[32][33];
    const int n0 = blockIdx.x * 32;
    const int k0 = blockIdx.y * 32;
#pragma unroll
    for (int i = 0; i < 4; ++i) {
        int kk = threadIdx.y + i * 8;
        t[kk][threadIdx.x] = w[(size_t)(k0 + kk) * N + n0 + threadIdx.x];
    }
    __syncthreads();
#pragma unroll
    for (int i = 0; i < 4; ++i) {
        int nn = threadIdx.y + i * 8;
        int kk = threadIdx.x;
        float v = t[kk][nn];
        __nv_bfloat16 h = __float2bfloat16_rn(v);
        __nv_bfloat16 l = __float2bfloat16_rn(v - __bfloat162float(h));
        size_t o = (size_t)(n0 + nn) * K + k0 + kk;
        hi[o] = h;
        lo[o] = l;
    }
}

// ---------------------------------------------------------------------------
// HMMA GEMM: C[M,N] fp32 = A[M,K] @ B^T, B stored [N,K], bf16 hi/lo 3-product.
// 128x128 block tile, BK=32, 256 threads (8 warps, 2x4), 64x32 warp tile.
// cp.async double-buffered smem. Smem rows padded to 40 bf16 (conflict-free).
// ---------------------------------------------------------------------------
#define BK 32
#define ASTRIDE 40                       // bf16 elems per smem row (32 + 8 pad)
#define TILE_B (128 * ASTRIDE * 2)       // 10240 bytes per tile
#define BUF_B  (4 * TILE_B)              // Ahi, Alo, Bhi, Blo
#define GEMM_SMEM (2 * BUF_B)            // 81920 bytes

__global__ __launch_bounds__(256, 1)
void gemm_hmma3_kernel(const __nv_bfloat16* __restrict__ Ahi,
                       const __nv_bfloat16* __restrict__ Alo,
                       const __nv_bfloat16* __restrict__ Bhi,
                       const __nv_bfloat16* __restrict__ Blo,
                       float* __restrict__ C, int N, int K)
{
    extern __shared__ char smem[];
    const uint32_t sbase = smem_u32(smem);
    const int tid = threadIdx.x;
    const int wid = tid >> 5;
    const int lane = tid & 31;
    const int grp = lane >> 2;      // 0..7
    const int tig = lane & 3;       // 0..3
    const int warp_m = wid >> 2;    // 0..1
    const int warp_n = wid & 3;     // 0..3
    const int rowBase = blockIdx.y * 128;
    const int colBase = blockIdx.x * 128;

    // gmem load mapping: per tile, thread covers f4 idx {tid, tid+256}:
    // row = idx>>2, c4 = idx&3  (128 rows x 4 float4 of 8 bf16)
    const int r0 = tid >> 2;
    const int c4 = tid & 3;

    const __nv_bfloat16* gsrc[4];
    gsrc[0] = Ahi + (size_t)rowBase * K;
    gsrc[1] = Alo + (size_t)rowBase * K;
    gsrc[2] = Bhi + (size_t)colBase * K;
    gsrc[3] = Blo + (size_t)colBase * K;

    float acc[4][4][4];
#pragma unroll
    for (int i = 0; i < 4; ++i)
#pragma unroll
        for (int j = 0; j < 4; ++j)
#pragma unroll
            for (int k = 0; k < 4; ++k) acc[i][j][k] = 0.0f;

    const int nstages = K / BK;

    // ---- pipelined load helper (macro to keep everything in regs) ----
#define LOAD_STAGE(s) do {                                                      \
        const int _k0 = (s) * BK;                                               \
        const uint32_t _buf = sbase + ((s) & 1) * BUF_B;                        \
        _Pragma("unroll")                                                       \
        for (int _t = 0; _t < 4; ++_t) {                                        \
            uint32_t _sm = _buf + _t * TILE_B;                                  \
            const __nv_bfloat16* _g = gsrc[_t] + _k0;                           \
            _Pragma("unroll")                                                   \
            for (int _j = 0; _j < 2; ++_j) {                                    \
                int _row = r0 + _j * 64;                                        \
                CP_ASYNC16(_sm + _row * (ASTRIDE * 2) + c4 * 16,                \
                           _g + (size_t)_row * K + c4 * 8);                     \
            }                                                                   \
        }                                                                       \
        CP_COMMIT();                                                            \
    } while (0)

    LOAD_STAGE(0);

    for (int s = 0; s < nstages; ++s) {
        if (s + 1 < nstages) { LOAD_STAGE(s + 1); CP_WAIT(1); }
        else                 { CP_WAIT(0); }
        __syncthreads();

        const uint32_t buf = sbase + (s & 1) * BUF_B;
        const uint32_t smAh = buf + 0 * TILE_B;
        const uint32_t smAl = buf + 1 * TILE_B;
        const uint32_t smBh = buf + 2 * TILE_B;
        const uint32_t smBl = buf + 3 * TILE_B;

#pragma unroll
        for (int kk = 0; kk < BK; kk += 16) {
            uint32_t ah[4][4], al[4][4], bh[4][2], bl[4][2];
            // A fragments: rows warp_m*64 + mt*16 + {grp, grp+8}, k = kk + tig*2 (+8)
#pragma unroll
            for (int mt = 0; mt < 4; ++mt) {
                int rbase = warp_m * 64 + mt * 16 + grp;
                uint32_t o00 = (uint32_t)(rbase * (ASTRIDE * 2) + (kk + tig * 2) * 2);
                uint32_t o10 = o00 + 8 * (ASTRIDE * 2);
                asm volatile("ld.shared.b32 %0, [%1];" : "=r"(ah[mt][0]) : "r"(smAh + o00));
                asm volatile("ld.shared.b32 %0, [%1];" : "=r"(ah[mt][1]) : "r"(smAh + o10));
                asm volatile("ld.shared.b32 %0, [%1];" : "=r"(ah[mt][2]) : "r"(smAh + o00 + 16));
                asm volatile("ld.shared.b32 %0, [%1];" : "=r"(ah[mt][3]) : "r"(smAh + o10 + 16));
                asm volatile("ld.shared.b32 %0, [%1];" : "=r"(al[mt][0]) : "r"(smAl + o00));
                asm volatile("ld.shared.b32 %0, [%1];" : "=r"(al[mt][1]) : "r"(smAl + o10));
                asm volatile("ld.shared.b32 %0, [%1];" : "=r"(al[mt][2]) : "r"(smAl + o00 + 16));
                asm volatile("ld.shared.b32 %0, [%1];" : "=r"(al[mt][3]) : "r"(smAl + o10 + 16));
            }
            // B fragments: n = warp_n*32 + nt*8 + grp, k = kk + tig*2 (+8)
#pragma unroll
            for (int nt = 0; nt < 4; ++nt) {
                int nbase = warp_n * 32 + nt * 8 + grp;
                uint32_t o = (uint32_t)(nbase * (ASTRIDE * 2) + (kk + tig * 2) * 2);
                asm volatile("ld.shared.b32 %0, [%1];" : "=r"(bh[nt][0]) : "r"(smBh + o));
                asm volatile("ld.shared.b32 %0, [%1];" : "=r"(bh[nt][1]) : "r"(smBh + o + 16));
                asm volatile("ld.shared.b32 %0, [%1];" : "=r"(bl[nt][0]) : "r"(smBl + o));
                asm volatile("ld.shared.b32 %0, [%1];" : "=r"(bl[nt][1]) : "r"(smBl + o + 16));
            }
#pragma unroll
            for (int mt = 0; mt < 4; ++mt)
#pragma unroll
                for (int nt = 0; nt < 4; ++nt) {
                    mma16816(acc[mt][nt], ah[mt], bh[nt]);
                    mma16816(acc[mt][nt], ah[mt], bl[nt]);
                    mma16816(acc[mt][nt], al[mt], bh[nt]);
                }
        }
        __syncthreads();
    }

    // Epilogue: direct stg.64 per fragment
#pragma unroll
    for (int mt = 0; mt < 4; ++mt) {
        int r = rowBase + warp_m * 64 + mt * 16 + grp;
#pragma unroll
        for (int nt = 0; nt < 4; ++nt) {
            int c = colBase + warp_n * 32 + nt * 8 + tig * 2;
            float2 v0 = make_float2(acc[mt][nt][0], acc[mt][nt][1]);
            float2 v1 = make_float2(acc[mt][nt][2], acc[mt][nt][3]);
            *(float2*)(C + (size_t)r * N + c) = v0;
            *(float2*)(C + (size_t)(r + 8) * N + c) = v1;
        }
    }
#undef LOAD_STAGE
}

// ---------------------------------------------------------------------------
// Causal flash attention, fp32 (unchanged; tensorize next round).
// ---------------------------------------------------------------------------
#define BQ  128
#define BKV 64

__global__ __launch_bounds__(128)
void attn_kernel(const float* __restrict__ qkv, float* __restrict__ y)
{
    const int qb  = blockIdx.x;
    const int bh  = blockIdx.y;
    const int b   = bh / NHEAD;
    const int h   = bh % NHEAD;
    const int tid = threadIdx.x;
    const int qi  = qb * BQ + tid;

    const int C3 = 3 * NEMBD;
    const float* base = qkv + (size_t)b * TSEQ * C3;

    const float* qptr = base + (size_t)qi * C3 + h * HDIM;
    float qreg[HDIM];
#pragma unroll
    for (int d = 0; d < HDIM; d += 4) {
        float4 t = *(const float4*)(qptr + d);
        qreg[d + 0] = t.x * 0.125f;
        qreg[d + 1] = t.y * 0.125f;
        qreg[d + 2] = t.z * 0.125f;
        qreg[d + 3] = t.w * 0.125f;
    }

    float o[HDIM];
#pragma unroll
    for (int d = 0; d < HDIM; ++d) o[d] = 0.0f;
    float mrow = -INFINITY;
    float lrow = 0.0f;

    __shared__ __align__(16) float Ks[BKV][HDIM];
    __shared__ __align__(16) float Vs[BKV][HDIM];

    const int nkb = (qb * BQ + BQ - 1) / BKV + 1;

    for (int kb = 0; kb < nkb; ++kb) {
        __syncthreads();
        const float* kbase = base + (size_t)(kb * BKV) * C3 + NEMBD + h * HDIM;
        const float* vbase = base + (size_t)(kb * BKV) * C3 + 2 * NEMBD + h * HDIM;
#pragma unroll
        for (int i = 0; i < (BKV * HDIM / 4) / 128; ++i) {
            int idx = tid + i * 128;
            int row = idx / (HDIM / 4);
            int c4i = idx % (HDIM / 4);
            *(float4*)(&Ks[row][c4i * 4]) = *(const float4*)(kbase + (size_t)row * C3 + c4i * 4);
            *(float4*)(&Vs[row][c4i * 4]) = *(const float4*)(vbase + (size_t)row * C3 + c4i * 4);
        }
        __syncthreads();

        const int jmax = min(BKV, qi - kb * BKV + 1);
        for (int j = 0; j < jmax; ++j) {
            float s = 0.0f;
#pragma unroll
            for (int d = 0; d < HDIM; d += 4) {
                float4 k4 = *(const float4*)(&Ks[j][d]);
                s += qreg[d + 0] * k4.x + qreg[d + 1] * k4.y
                   + qreg[d + 2] * k4.z + qreg[d + 3] * k4.w;
            }
            if (s > mrow) {
                float alpha = __expf(mrow - s);
                lrow *= alpha;
#pragma unroll
                for (int d = 0; d < HDIM; ++d) o[d] *= alpha;
                mrow = s;
            }
            float p = __expf(s - mrow);
            lrow += p;
#pragma unroll
            for (int d = 0; d < HDIM; d += 4) {
                float4 v4 = *(const float4*)(&Vs[j][d]);
                o[d + 0] += p * v4.x;
                o[d + 1] += p * v4.y;
                o[d + 2] += p * v4.z;
                o[d + 3] += p * v4.w;
            }
        }
    }

    const float inv_l = 1.0f / lrow;
    float* yptr = y + (size_t)(b * TSEQ + qi) * NEMBD + h * HDIM;
#pragma unroll
    for (int d = 0; d < HDIM; d += 4) {
        float4 t = make_float4(o[d] * inv_l, o[d + 1] * inv_l,
                               o[d + 2] * inv_l, o[d + 3] * inv_l);
        *(float4*)(yptr + d) = t;
    }
}

// ---------------------------------------------------------------------------
// Launch
// ---------------------------------------------------------------------------
extern "C" void kernel_launch(void* const* d_in, const int* in_sizes, int n_in,
                              void* d_out, int out_size)
{
    const float* x      = (const float*)d_in[0]; // [4,2048,1024]
    const float* w_attn = (const float*)d_in[1]; // [1024,3072]
    const float* w_proj = (const float*)d_in[2]; // [1024,1024]
    float* out = (float*)d_out;                  // [4,2048,1024]

    float *qkv, *y;
    __nv_bfloat16 *ahi, *alo, *wqhi, *wqlo, *wphi, *wplo;
    cudaGetSymbolAddress((void**)&qkv, g_qkv);
    cudaGetSymbolAddress((void**)&y, g_y);
    cudaGetSymbolAddress((void**)&ahi, g_a_hi);
    cudaGetSymbolAddress((void**)&alo, g_a_lo);
    cudaGetSymbolAddress((void**)&wqhi, g_wq_hi);
    cudaGetSymbolAddress((void**)&wqlo, g_wq_lo);
    cudaGetSymbolAddress((void**)&wphi, g_wp_hi);
    cudaGetSymbolAddress((void**)&wplo, g_wp_lo);

    cudaFuncSetAttribute(gemm_hmma3_kernel,
                         cudaFuncAttributeMaxDynamicSharedMemorySize, GEMM_SMEM);

    const int M = BATCH * TSEQ;   // 8192
    const int K = NEMBD;          // 1024
    const int N1 = 3 * NEMBD;     // 3072
    const int N2 = NEMBD;         // 1024

    // Split x -> bf16 hi/lo
    {
        int n4 = (M * K) / 4;
        split_kernel<<<(n4 + 255) / 256, 256>>>(x, ahi, alo, n4);
    }
    // Transpose+split weights
    {
        dim3 g1(N1 / 32, K / 32);
        tsplit_kernel<<<g1, dim3(32, 8)>>>(w_attn, wqhi, wqlo, K, N1);
        dim3 g2(N2 / 32, K / 32);
        tsplit_kernel<<<g2, dim3(32, 8)>>>(w_proj, wphi, wplo, K, N2);
    }
    // Stage 1: qkv = x @ w_attn  (HMMA)
    {
        dim3 grid(N1 / 128, M / 128);
        gemm_hmma3_kernel<<<grid, 256, GEMM_SMEM>>>(ahi, alo, wqhi, wqlo, qkv, N1, K);
    }
    // Stage 2: attention
    {
        dim3 grid(TSEQ / BQ, BATCH * NHEAD);
        attn_kernel<<<grid, 128>>>(qkv, y);
    }
    // Split y -> bf16 hi/lo (reuse buffers)
    {
        int n4 = (M * K) / 4;
        split_kernel<<<(n4 + 255) / 256, 256>>>(y, ahi, alo, n4);
    }
    // Stage 3: out = y @ w_proj  (HMMA)
    {
        dim3 grid(N2 / 128, M / 128);
        gemm_hmma3_kernel<<<grid, 256, GEMM_SMEM>>>(ahi, alo, wphi, wplo, out, N2, K);
    }
}

// round 4
// speedup vs baseline: 2.8018x; 2.0190x over previous
#include <cuda_runtime.h>
#include <cuda_bf16.h>
#include <math.h>
#include <stdint.h>

// Problem constants
#define NEMBD 1024
#define NHEAD 16
#define HDIM  64
#define TSEQ  2048
#define BATCH 4
#define BH    (BATCH * NHEAD)
#define QSCALE 0.18033688011112042f   // 0.125 * log2(e)

// ---------------------------------------------------------------------------
// Scratch (device globals; allocation in kernel_launch is forbidden)
// ---------------------------------------------------------------------------
__device__ float g_qkv[(size_t)BATCH * TSEQ * 3 * NEMBD]; // [B,T,3C] fp32
__device__ __nv_bfloat16 g_a_hi[(size_t)BATCH * TSEQ * NEMBD]; // GEMM A operand (x, then y)
__device__ __nv_bfloat16 g_a_lo[(size_t)BATCH * TSEQ * NEMBD];
__device__ __nv_bfloat16 g_wq_hi[(size_t)3 * NEMBD * NEMBD];   // w_attn^T [3072][1024]
__device__ __nv_bfloat16 g_wq_lo[(size_t)3 * NEMBD * NEMBD];
__device__ __nv_bfloat16 g_wp_hi[(size_t)NEMBD * NEMBD];       // w_proj^T [1024][1024]
__device__ __nv_bfloat16 g_wp_lo[(size_t)NEMBD * NEMBD];
// Attention operand buffers
__device__ __nv_bfloat16 g_q_hi[(size_t)BH * TSEQ * HDIM];  // [bh][t][d], pre-scaled
__device__ __nv_bfloat16 g_q_lo[(size_t)BH * TSEQ * HDIM];
__device__ __nv_bfloat16 g_k_hi[(size_t)BH * TSEQ * HDIM];  // [bh][t][d]
__device__ __nv_bfloat16 g_k_lo[(size_t)BH * TSEQ * HDIM];
__device__ __nv_bfloat16 g_vt_hi[(size_t)BH * HDIM * TSEQ]; // [bh][d][t]
__device__ __nv_bfloat16 g_vt_lo[(size_t)BH * HDIM * TSEQ];

// ---------------------------------------------------------------------------
// PTX helpers (base ISA only — harness targets sm_103 without 'a')
// ---------------------------------------------------------------------------
__device__ __forceinline__ uint32_t smem_u32(const void* p) {
    uint32_t a;
    asm("{ .reg .u64 t; cvta.to.shared.u64 t, %1; cvt.u32.u64 %0, t; }" : "=r"(a) : "l"(p));
    return a;
}
#define CP_ASYNC16(sm, gm) \
    asm volatile("cp.async.cg.shared.global [%0], [%1], 16;" :: "r"(sm), "l"(gm))
#define CP_COMMIT() asm volatile("cp.async.commit_group;" ::: "memory")
#define CP_WAIT(n)  asm volatile("cp.async.wait_group %0;" :: "n"(n) : "memory")

__device__ __forceinline__ void mma16816(float* c, const uint32_t* a, const uint32_t* b) {
    asm volatile(
        "mma.sync.aligned.m16n8k16.row.col.f32.bf16.bf16.f32 "
        "{%0,%1,%2,%3}, {%4,%5,%6,%7}, {%8,%9}, {%0,%1,%2,%3};"
        : "+f"(c[0]), "+f"(c[1]), "+f"(c[2]), "+f"(c[3])
        : "r"(a[0]), "r"(a[1]), "r"(a[2]), "r"(a[3]), "r"(b[0]), "r"(b[1]));
}
__device__ __forceinline__ void mma_bb(float* c, const uint32_t* a, uint32_t b0, uint32_t b1) {
    asm volatile(
        "mma.sync.aligned.m16n8k16.row.col.f32.bf16.bf16.f32 "
        "{%0,%1,%2,%3}, {%4,%5,%6,%7}, {%8,%9}, {%0,%1,%2,%3};"
        : "+f"(c[0]), "+f"(c[1]), "+f"(c[2]), "+f"(c[3])
        : "r"(a[0]), "r"(a[1]), "r"(a[2]), "r"(a[3]), "r"(b0), "r"(b1));
}
// pack (lo,hi) floats into bf16x2 word: low half = lo, high half = hi
__device__ __forceinline__ uint32_t pack_bf16(float lo, float hi) {
    uint32_t r;
    asm("cvt.rn.bf16x2.f32 %0, %1, %2;" : "=r"(r) : "f"(hi), "f"(lo));
    return r;
}
// FFMA-only 2^t for t <= 0 (avoids MUFU). err ~2e-9.
__device__ __forceinline__ float exp2p(float t) {
    t = fmaxf(t, -126.0f);
    float fi = rintf(t);
    float f = t - fi;
    float p = 0.0013333558f;
    p = fmaf(p, f, 0.0096181291f);
    p = fmaf(p, f, 0.0555041087f);
    p = fmaf(p, f, 0.2402265070f);
    p = fmaf(p, f, 0.6931471806f);
    p = fmaf(p, f, 1.0f);
    int ii = (int)fi;
    return p * __int_as_float((uint32_t)(ii + 127) << 23);
}

// ---------------------------------------------------------------------------
// Conversion kernels
// ---------------------------------------------------------------------------
__global__ __launch_bounds__(256)
void split_kernel(const float* __restrict__ in, __nv_bfloat16* __restrict__ hi,
                  __nv_bfloat16* __restrict__ lo, int n4)
{
    int idx = blockIdx.x * blockDim.x + threadIdx.x;
    if (idx >= n4) return;
    float4 v = ((const float4*)in)[idx];
    __nv_bfloat16 h[4], l[4];
    float f[4] = {v.x, v.y, v.z, v.w};
#pragma unroll
    for (int i = 0; i < 4; ++i) {
        h[i] = __float2bfloat16_rn(f[i]);
        l[i] = __float2bfloat16_rn(f[i] - __bfloat162float(h[i]));
    }
    ((uint2*)hi)[idx] = *(const uint2*)h;
    ((uint2*)lo)[idx] = *(const uint2*)l;
}

// w [K][N] fp32 -> hi/lo bf16 [N][K] (transposed). Block (32,8), grid (N/32, K/32).
__global__ __launch_bounds__(256)
void tsplit_kernel(const float* __restrict__ w, __nv_bfloat16* __restrict__ hi,
                   __nv_bfloat16* __restrict__ lo, int K, int N)
{
    __shared__ float t[32][33];
    const int n0 = blockIdx.x * 32;
    const int k0 = blockIdx.y * 32;
#pragma unroll
    for (int i = 0; i < 4; ++i) {
        int kk = threadIdx.y + i * 8;
        t[kk][threadIdx.x] = w[(size_t)(k0 + kk) * N + n0 + threadIdx.x];
    }
    __syncthreads();
#pragma unroll
    for (int i = 0; i < 4; ++i) {
        int nn = threadIdx.y + i * 8;
        int kk = threadIdx.x;
        float v = t[kk][nn];
        __nv_bfloat16 h = __float2bfloat16_rn(v);
        __nv_bfloat16 l = __float2bfloat16_rn(v - __bfloat162float(h));
        size_t o = (size_t)(n0 + nn) * K + k0 + kk;
        hi[o] = h;
        lo[o] = l;
    }
}

// Extract Q (scaled by QSCALE) and K from qkv into [bh][t][64] bf16 hi/lo.
__global__ __launch_bounds__(256)
void qk_split_kernel(const float* __restrict__ qkv,
                     __nv_bfloat16* __restrict__ qhi, __nv_bfloat16* __restrict__ qlo,
                     __nv_bfloat16* __restrict__ khi, __nv_bfloat16* __restrict__ klo)
{
    int idx = blockIdx.x * 256 + threadIdx.x;     // 0 .. BH*T*16-1 (float4 units)
    int d4 = idx & 15;
    int t  = (idx >> 4) & (TSEQ - 1);
    int bh = idx >> 15;
    int b = bh >> 4, h = bh & 15;
    const float* src = qkv + ((size_t)(b * TSEQ + t)) * (3 * NEMBD) + h * HDIM + d4 * 4;
    size_t dst = ((size_t)(bh * TSEQ + t)) * HDIM / 4 + d4; // uint2 units... careful
    // Q (scaled)
    {
        float4 v = *(const float4*)src;
        float f[4] = {v.x * QSCALE, v.y * QSCALE, v.z * QSCALE, v.w * QSCALE};
        __nv_bfloat16 hh[4], ll[4];
#pragma unroll
        for (int i = 0; i < 4; ++i) {
            hh[i] = __float2bfloat16_rn(f[i]);
            ll[i] = __float2bfloat16_rn(f[i] - __bfloat162float(hh[i]));
        }
        ((uint2*)qhi)[dst] = *(const uint2*)hh;
        ((uint2*)qlo)[dst] = *(const uint2*)ll;
    }
    // K (unscaled)
    {
        float4 v = *(const float4*)(src + NEMBD);
        float f[4] = {v.x, v.y, v.z, v.w};
        __nv_bfloat16 hh[4], ll[4];
#pragma unroll
        for (int i = 0; i < 4; ++i) {
            hh[i] = __float2bfloat16_rn(f[i]);
            ll[i] = __float2bfloat16_rn(f[i] - __bfloat162float(hh[i]));
        }
        ((uint2*)khi)[dst] = *(const uint2*)hh;
        ((uint2*)klo)[dst] = *(const uint2*)ll;
    }
}

// V from qkv -> transposed [bh][d][t] bf16 hi/lo. Block (32,8), grid (T/32, 2, BH).
__global__ __launch_bounds__(256)
void v_tsplit_kernel(const float* __restrict__ qkv,
                     __nv_bfloat16* __restrict__ vhi, __nv_bfloat16* __restrict__ vlo)
{
    __shared__ float sm[32][33];
    const int t0 = blockIdx.x * 32;
    const int d0 = blockIdx.y * 32;
    const int bh = blockIdx.z;
    const int b = bh >> 4, h = bh & 15;
#pragma unroll
    for (int i = 0; i < 4; ++i) {
        int t = t0 + threadIdx.y + i * 8;
        sm[threadIdx.y + i * 8][threadIdx.x] =
            qkv[((size_t)(b * TSEQ + t)) * (3 * NEMBD) + 2 * NEMBD + h * HDIM + d0 + threadIdx.x];
    }
    __syncthreads();
#pragma unroll
    for (int i = 0; i < 4; ++i) {
        int d = d0 + threadIdx.y + i * 8;
        int t = t0 + threadIdx.x;
        float v = sm[threadIdx.x][threadIdx.y + i * 8];
        __nv_bfloat16 hh = __float2bfloat16_rn(v);
        __nv_bfloat16 ll = __float2bfloat16_rn(v - __bfloat162float(hh));
        size_t o = ((size_t)(bh * HDIM + d)) * TSEQ + t;
        vhi[o] = hh;
        vlo[o] = ll;
    }
}

// ---------------------------------------------------------------------------
// HMMA GEMM (unchanged from R3): C = A @ B^T, bf16 hi/lo 3-product.
// ---------------------------------------------------------------------------
#define BK 32
#define ASTRIDE 40
#define TILE_B (128 * ASTRIDE * 2)
#define BUF_B  (4 * TILE_B)
#define GEMM_SMEM (2 * BUF_B)

__global__ __launch_bounds__(256, 1)
void gemm_hmma3_kernel(const __nv_bfloat16* __restrict__ Ahi,
                       const __nv_bfloat16* __restrict__ Alo,
                       const __nv_bfloat16* __restrict__ Bhi,
                       const __nv_bfloat16* __restrict__ Blo,
                       float* __restrict__ C, int N, int K)
{
    extern __shared__ char smem[];
    const uint32_t sbase = smem_u32(smem);
    const int tid = threadIdx.x;
    const int wid = tid >> 5;
    const int lane = tid & 31;
    const int grp = lane >> 2;
    const int tig = lane & 3;
    const int warp_m = wid >> 2;
    const int warp_n = wid & 3;
    const int rowBase = blockIdx.y * 128;
    const int colBase = blockIdx.x * 128;

    const int r0 = tid >> 2;
    const int c4 = tid & 3;

    const __nv_bfloat16* gsrc[4];
    gsrc[0] = Ahi + (size_t)rowBase * K;
    gsrc[1] = Alo + (size_t)rowBase * K;
    gsrc[2] = Bhi + (size_t)colBase * K;
    gsrc[3] = Blo + (size_t)colBase * K;

    float acc[4][4][4];
#pragma unroll
    for (int i = 0; i < 4; ++i)
#pragma unroll
        for (int j = 0; j < 4; ++j)
#pragma unroll
            for (int k = 0; k < 4; ++k) acc[i][j][k] = 0.0f;

    const int nstages = K / BK;

#define LOAD_STAGE(s) do {                                                      \
        const int _k0 = (s) * BK;                                               \
        const uint32_t _buf = sbase + ((s) & 1) * BUF_B;                        \
        _Pragma("unroll")                                                       \
        for (int _t = 0; _t < 4; ++_t) {                                        \
            uint32_t _sm = _buf + _t * TILE_B;                                  \
            const __nv_bfloat16* _g = gsrc[_t] + _k0;                           \
            _Pragma("unroll")                                                   \
            for (int _j = 0; _j < 2; ++_j) {                                    \
                int _row = r0 + _j * 64;                                        \
                CP_ASYNC16(_sm + _row * (ASTRIDE * 2) + c4 * 16,                \
                           _g + (size_t)_row * K + c4 * 8);                     \
            }                                                                   \
        }                                                                       \
        CP_COMMIT();                                                            \
    } while (0)

    LOAD_STAGE(0);

    for (int s = 0; s < nstages; ++s) {
        if (s + 1 < nstages) { LOAD_STAGE(s + 1); CP_WAIT(1); }
        else                 { CP_WAIT(0); }
        __syncthreads();

        const uint32_t buf = sbase + (s & 1) * BUF_B;
        const uint32_t smAh = buf + 0 * TILE_B;
        const uint32_t smAl = buf + 1 * TILE_B;
        const uint32_t smBh = buf + 2 * TILE_B;
        const uint32_t smBl = buf + 3 * TILE_B;

#pragma unroll
        for (int kk = 0; kk < BK; kk += 16) {
            uint32_t ah[4][4], al[4][4], bhf[4][2], blf[4][2];
#pragma unroll
            for (int mt = 0; mt < 4; ++mt) {
                int rbase = warp_m * 64 + mt * 16 + grp;
                uint32_t o00 = (uint32_t)(rbase * (ASTRIDE * 2) + (kk + tig * 2) * 2);
                uint32_t o10 = o00 + 8 * (ASTRIDE * 2);
                asm volatile("ld.shared.b32 %0, [%1];" : "=r"(ah[mt][0]) : "r"(smAh + o00));
                asm volatile("ld.shared.b32 %0, [%1];" : "=r"(ah[mt][1]) : "r"(smAh + o10));
                asm volatile("ld.shared.b32 %0, [%1];" : "=r"(ah[mt][2]) : "r"(smAh + o00 + 16));
                asm volatile("ld.shared.b32 %0, [%1];" : "=r"(ah[mt][3]) : "r"(smAh + o10 + 16));
                asm volatile("ld.shared.b32 %0, [%1];" : "=r"(al[mt][0]) : "r"(smAl + o00));
                asm volatile("ld.shared.b32 %0, [%1];" : "=r"(al[mt][1]) : "r"(smAl + o10));
                asm volatile("ld.shared.b32 %0, [%1];" : "=r"(al[mt][2]) : "r"(smAl + o00 + 16));
                asm volatile("ld.shared.b32 %0, [%1];" : "=r"(al[mt][3]) : "r"(smAl + o10 + 16));
            }
#pragma unroll
            for (int nt = 0; nt < 4; ++nt) {
                int nbase = warp_n * 32 + nt * 8 + grp;
                uint32_t o = (uint32_t)(nbase * (ASTRIDE * 2) + (kk + tig * 2) * 2);
                asm volatile("ld.shared.b32 %0, [%1];" : "=r"(bhf[nt][0]) : "r"(smBh + o));
                asm volatile("ld.shared.b32 %0, [%1];" : "=r"(bhf[nt][1]) : "r"(smBh + o + 16));
                asm volatile("ld.shared.b32 %0, [%1];" : "=r"(blf[nt][0]) : "r"(smBl + o));
                asm volatile("ld.shared.b32 %0, [%1];" : "=r"(blf[nt][1]) : "r"(smBl + o + 16));
            }
#pragma unroll
            for (int mt = 0; mt < 4; ++mt)
#pragma unroll
                for (int nt = 0; nt < 4; ++nt) {
                    mma16816(acc[mt][nt], ah[mt], bhf[nt]);
                    mma16816(acc[mt][nt], ah[mt], blf[nt]);
                    mma16816(acc[mt][nt], al[mt], bhf[nt]);
                }
        }
        __syncthreads();
    }

#pragma unroll
    for (int mt = 0; mt < 4; ++mt) {
        int r = rowBase + warp_m * 64 + mt * 16 + grp;
#pragma unroll
        for (int nt = 0; nt < 4; ++nt) {
            int c = colBase + warp_n * 32 + nt * 8 + tig * 2;
            *(float2*)(C + (size_t)r * N + c) = make_float2(acc[mt][nt][0], acc[mt][nt][1]);
            *(float2*)(C + (size_t)(r + 8) * N + c) = make_float2(acc[mt][nt][2], acc[mt][nt][3]);
        }
    }
#undef LOAD_STAGE
}

// ---------------------------------------------------------------------------
// HMMA flash attention. 128q x 128kv tiles, 8 warps x 16 q-rows.
// Q pre-scaled by 0.125*log2e; softmax in base-2 with FFMA-only exp2.
// Writes y directly as packed bf16 hi/lo pairs for the proj GEMM.
// ---------------------------------------------------------------------------
#define AQ  128
#define AKV 128
#define KSW 36   // K/Q smem row stride (words); bank-complete for B/A frag loads
#define VSW 68   // V^T smem row stride (words)
#define QHI_W 0
#define QLO_W 4608
#define STG0_W 9216
#define STG_SZ_W 17920
#define KHI_W 0
#define KLO_W 4608
#define VHI_W 9216
#define VLO_W 13568
#define ATTN_SMEM_B ((STG0_W + 2 * STG_SZ_W) * 4)   // 180224 bytes

__global__ __launch_bounds__(256, 1)
void attn_hmma_kernel(const __nv_bfloat16* __restrict__ Qh, const __nv_bfloat16* __restrict__ Ql,
                      const __nv_bfloat16* __restrict__ Kh, const __nv_bfloat16* __restrict__ Kl,
                      const __nv_bfloat16* __restrict__ Vth, const __nv_bfloat16* __restrict__ Vtl,
                      uint32_t* __restrict__ yhi, uint32_t* __restrict__ ylo)
{
    extern __shared__ uint32_t smw[];
    const uint32_t sbase = smem_u32(smw);
    const int tid = threadIdx.x;
    const int warp = tid >> 5;
    const int lane = tid & 31;
    const int grp = lane >> 2;
    const int tig = lane & 3;
    const int qb = (int)(gridDim.x - 1 - blockIdx.x);  // heavy tiles first
    const int bh = blockIdx.y;
    const int q0 = qb * AQ;
    const size_t bhT = (size_t)bh * TSEQ;

    // ---- issue Q loads + KV stage 0 loads ----
#pragma unroll
    for (int i = 0; i < 4; ++i) {
        int idx = tid + i * 256;
        int r = idx >> 3, c = idx & 7;
        CP_ASYNC16(sbase + (QHI_W + r * KSW) * 4 + c * 16, Qh + (bhT + q0 + r) * HDIM + c * 8);
        CP_ASYNC16(sbase + (QLO_W + r * KSW) * 4 + c * 16, Ql + (bhT + q0 + r) * HDIM + c * 8);
    }
    CP_COMMIT();

#define LOAD_KV(kb_, st_) do {                                                          \
        const int _kv0 = (kb_) * AKV;                                                  \
        const uint32_t _sb = sbase + (STG0_W + (st_) * STG_SZ_W) * 4;                   \
        _Pragma("unroll")                                                               \
        for (int _i = 0; _i < 4; ++_i) {                                                \
            int _idx = tid + _i * 256;                                                  \
            int _r = _idx >> 3, _c = _idx & 7;                                          \
            CP_ASYNC16(_sb + (KHI_W + _r * KSW) * 4 + _c * 16,                          \
                       Kh + (bhT + _kv0 + _r) * HDIM + _c * 8);                         \
            CP_ASYNC16(_sb + (KLO_W + _r * KSW) * 4 + _c * 16,                          \
                       Kl + (bhT + _kv0 + _r) * HDIM + _c * 8);                         \
        }                                                                               \
        _Pragma("unroll")                                                               \
        for (int _i = 0; _i < 4; ++_i) {                                                \
            int _idx = tid + _i * 256;                                                  \
            int _r = _idx >> 4, _c = _idx & 15;                                         \
            CP_ASYNC16(_sb + (VHI_W + _r * VSW) * 4 + _c * 16,                          \
                       Vth + ((size_t)bh * HDIM + _r) * TSEQ + _kv0 + _c * 8);          \
            CP_ASYNC16(_sb + (VLO_W + _r * VSW) * 4 + _c * 16,                          \
                       Vtl + ((size_t)bh * HDIM + _r) * TSEQ + _kv0 + _c * 8);          \
        }                                                                               \
        CP_COMMIT();                                                                    \
    } while (0)

    LOAD_KV(0, 0);
    CP_WAIT(0);
    __syncthreads();

    // ---- Q fragments in registers (A-operand layout) ----
    uint32_t qfh[4][4], qfl[4][4];
    {
        const int r0 = warp * 16 + grp;
#pragma unroll
        for (int ks = 0; ks < 4; ++ks) {
            uint32_t b0 = (uint32_t)(QHI_W + r0 * KSW + ks * 8 + tig);
            qfh[ks][0] = smw[b0];
            qfh[ks][1] = smw[b0 + 8 * KSW];
            qfh[ks][2] = smw[b0 + 4];
            qfh[ks][3] = smw[b0 + 8 * KSW + 4];
            uint32_t b1 = b0 + (QLO_W - QHI_W);
            qfl[ks][0] = smw[b1];
            qfl[ks][1] = smw[b1 + 8 * KSW];
            qfl[ks][2] = smw[b1 + 4];
            qfl[ks][3] = smw[b1 + 8 * KSW + 4];
        }
    }

    float o[8][4];
#pragma unroll
    for (int i = 0; i < 8; ++i)
#pragma unroll
        for (int j = 0; j < 4; ++j) o[i][j] = 0.0f;
    float m0 = -1e30f, m1 = -1e30f, l0 = 0.0f, l1 = 0.0f;

    const int nkb = qb + 1;
    for (int kb = 0; kb < nkb; ++kb) {
        if (kb) { CP_WAIT(0); __syncthreads(); }
        if (kb + 1 < nkb) LOAD_KV(kb + 1, (kb + 1) & 1);

        const uint32_t stw = STG0_W + (kb & 1) * STG_SZ_W;
        const uint32_t khW = stw + KHI_W, klW = stw + KLO_W;
        const uint32_t vhW = stw + VHI_W, vlW = stw + VLO_W;

        // ---- S = Q @ K^T (3 products) ----
        float s[16][4];
#pragma unroll
        for (int nt = 0; nt < 16; ++nt) {
            s[nt][0] = s[nt][1] = s[nt][2] = s[nt][3] = 0.0f;
            const uint32_t rowW = (uint32_t)((nt * 8 + grp) * KSW + tig);
#pragma unroll
            for (int ks = 0; ks < 4; ++ks) {
                uint32_t oh = khW + rowW + ks * 8;
                uint32_t bh0 = smw[oh], bh1 = smw[oh + 4];
                uint32_t ol = klW + rowW + ks * 8;
                uint32_t bl0 = smw[ol], bl1 = smw[ol + 4];
                mma_bb(s[nt], qfh[ks], bh0, bh1);
                mma_bb(s[nt], qfl[ks], bh0, bh1);
                mma_bb(s[nt], qfh[ks], bl0, bl1);
            }
        }

        // ---- causal mask on diagonal block ----
        if (kb == qb) {
            const int r0 = warp * 16 + grp;
            const int r1 = r0 + 8;
#pragma unroll
            for (int nt = 0; nt < 16; ++nt) {
                int c0 = nt * 8 + tig * 2;
                if (c0 > r0)     s[nt][0] = -1e30f;
                if (c0 + 1 > r0) s[nt][1] = -1e30f;
                if (c0 > r1)     s[nt][2] = -1e30f;
                if (c0 + 1 > r1) s[nt][3] = -1e30f;
            }
        }

        // ---- online softmax (base-2 domain) ----
        float mx0 = -1e30f, mx1 = -1e30f;
#pragma unroll
        for (int nt = 0; nt < 16; ++nt) {
            mx0 = fmaxf(mx0, fmaxf(s[nt][0], s[nt][1]));
            mx1 = fmaxf(mx1, fmaxf(s[nt][2], s[nt][3]));
        }
        mx0 = fmaxf(mx0, __shfl_xor_sync(0xffffffffu, mx0, 1));
        mx0 = fmaxf(mx0, __shfl_xor_sync(0xffffffffu, mx0, 2));
        mx1 = fmaxf(mx1, __shfl_xor_sync(0xffffffffu, mx1, 1));
        mx1 = fmaxf(mx1, __shfl_xor_sync(0xffffffffu, mx1, 2));
        float mn0 = fmaxf(m0, mx0), mn1 = fmaxf(m1, mx1);
        float a0 = exp2p(m0 - mn0), a1 = exp2p(m1 - mn1);
        m0 = mn0; m1 = mn1;
        l0 *= a0; l1 *= a1;
#pragma unroll
        for (int nt = 0; nt < 8; ++nt) {
            o[nt][0] *= a0; o[nt][1] *= a0;
            o[nt][2] *= a1; o[nt][3] *= a1;
        }
        float sum0 = 0.0f, sum1 = 0.0f;
#pragma unroll
        for (int nt = 0; nt < 16; ++nt) {
            float p0 = exp2p(s[nt][0] - m0);
            float p1 = exp2p(s[nt][1] - m0);
            float p2 = exp2p(s[nt][2] - m1);
            float p3 = exp2p(s[nt][3] - m1);
            sum0 += p0 + p1; sum1 += p2 + p3;
            s[nt][0] = p0; s[nt][1] = p1; s[nt][2] = p2; s[nt][3] = p3;
        }
        l0 += sum0; l1 += sum1;

        // ---- O += P @ V (3 products, P hi/lo repacked from S regs) ----
#pragma unroll
        for (int j = 0; j < 8; ++j) {
            uint32_t ah4[4], al4[4];
#pragma unroll
            for (int u = 0; u < 2; ++u) {
                const float* pv = s[2 * j + u];
                uint32_t h01 = pack_bf16(pv[0], pv[1]);
                uint32_t h23 = pack_bf16(pv[2], pv[3]);
                float r0f = __uint_as_float(h01 << 16);
                float r1f = __uint_as_float(h01 & 0xffff0000u);
                float r2f = __uint_as_float(h23 << 16);
                float r3f = __uint_as_float(h23 & 0xffff0000u);
                ah4[u * 2 + 0] = h01;
                ah4[u * 2 + 1] = h23;
                al4[u * 2 + 0] = pack_bf16(pv[0] - r0f, pv[1] - r1f);
                al4[u * 2 + 1] = pack_bf16(pv[2] - r2f, pv[3] - r3f);
            }
#pragma unroll
            for (int nt = 0; nt < 8; ++nt) {
                const uint32_t rowW = (uint32_t)((nt * 8 + grp) * VSW + j * 8 + tig);
                uint32_t vh0 = smw[vhW + rowW], vh1 = smw[vhW + rowW + 4];
                uint32_t vl0 = smw[vlW + rowW], vl1 = smw[vlW + rowW + 4];
                mma_bb(o[nt], ah4, vh0, vh1);
                mma_bb(o[nt], al4, vh0, vh1);
                mma_bb(o[nt], ah4, vl0, vl1);
            }
        }
        __syncthreads();
    }

    // ---- epilogue: normalize and store packed bf16 hi/lo y ----
    l0 += __shfl_xor_sync(0xffffffffu, l0, 1);
    l0 += __shfl_xor_sync(0xffffffffu, l0, 2);
    l1 += __shfl_xor_sync(0xffffffffu, l1, 1);
    l1 += __shfl_xor_sync(0xffffffffu, l1, 2);
    const float inv0 = 1.0f / l0, inv1 = 1.0f / l1;

    const int b = bh >> 4, h = bh & 15;
    const int rowg = q0 + warp * 16 + grp;
    const size_t base0 = ((size_t)(b * TSEQ) + rowg) * (NEMBD / 2) + h * (HDIM / 2);
    const size_t base1 = base0 + 8 * (NEMBD / 2);
#pragma unroll
    for (int nt = 0; nt < 8; ++nt) {
        int cw = nt * 4 + tig;
        {
            float f0 = o[nt][0] * inv0, f1 = o[nt][1] * inv0;
            uint32_t hp = pack_bf16(f0, f1);
            float r0f = __uint_as_float(hp << 16);
            float r1f = __uint_as_float(hp & 0xffff0000u);
            yhi[base0 + cw] = hp;
            ylo[base0 + cw] = pack_bf16(f0 - r0f, f1 - r1f);
        }
        {
            float f0 = o[nt][2] * inv1, f1 = o[nt][3] * inv1;
            uint32_t hp = pack_bf16(f0, f1);
            float r0f = __uint_as_float(hp << 16);
            float r1f = __uint_as_float(hp & 0xffff0000u);
            yhi[base1 + cw] = hp;
            ylo[base1 + cw] = pack_bf16(f0 - r0f, f1 - r1f);
        }
    }
#undef LOAD_KV
}

// ---------------------------------------------------------------------------
// Launch
// ---------------------------------------------------------------------------
extern "C" void kernel_launch(void* const* d_in, const int* in_sizes, int n_in,
                              void* d_out, int out_size)
{
    const float* x      = (const float*)d_in[0]; // [4,2048,1024]
    const float* w_attn = (const float*)d_in[1]; // [1024,3072]
    const float* w_proj = (const float*)d_in[2]; // [1024,1024]
    float* out = (float*)d_out;                  // [4,2048,1024]

    float* qkv;
    __nv_bfloat16 *ahi, *alo, *wqhi, *wqlo, *wphi, *wplo;
    __nv_bfloat16 *qhi, *qlo, *khi, *klo, *vthi, *vtlo;
    cudaGetSymbolAddress((void**)&qkv, g_qkv);
    cudaGetSymbolAddress((void**)&ahi, g_a_hi);
    cudaGetSymbolAddress((void**)&alo, g_a_lo);
    cudaGetSymbolAddress((void**)&wqhi, g_wq_hi);
    cudaGetSymbolAddress((void**)&wqlo, g_wq_lo);
    cudaGetSymbolAddress((void**)&wphi, g_wp_hi);
    cudaGetSymbolAddress((void**)&wplo, g_wp_lo);
    cudaGetSymbolAddress((void**)&qhi, g_q_hi);
    cudaGetSymbolAddress((void**)&qlo, g_q_lo);
    cudaGetSymbolAddress((void**)&khi, g_k_hi);
    cudaGetSymbolAddress((void**)&klo, g_k_lo);
    cudaGetSymbolAddress((void**)&vthi, g_vt_hi);
    cudaGetSymbolAddress((void**)&vtlo, g_vt_lo);

    cudaFuncSetAttribute(gemm_hmma3_kernel,
                         cudaFuncAttributeMaxDynamicSharedMemorySize, GEMM_SMEM);
    cudaFuncSetAttribute(attn_hmma_kernel,
                         cudaFuncAttributeMaxDynamicSharedMemorySize, ATTN_SMEM_B);

    const int M = BATCH * TSEQ;   // 8192
    const int K = NEMBD;          // 1024
    const int N1 = 3 * NEMBD;     // 3072
    const int N2 = NEMBD;         // 1024

    // Split x -> bf16 hi/lo (A operand of GEMM1)
    {
        int n4 = (M * K) / 4;
        split_kernel<<<(n4 + 255) / 256, 256>>>(x, ahi, alo, n4);
    }
    // Transpose+split weights
    {
        dim3 g1(N1 / 32, K / 32);
        tsplit_kernel<<<g1, dim3(32, 8)>>>(w_attn, wqhi, wqlo, K, N1);
        dim3 g2(N2 / 32, K / 32);
        tsplit_kernel<<<g2, dim3(32, 8)>>>(w_proj, wphi, wplo, K, N2);
    }
    // Stage 1: qkv = x @ w_attn  (HMMA)
    {
        dim3 grid(N1 / 128, M / 128);
        gemm_hmma3_kernel<<<grid, 256, GEMM_SMEM>>>(ahi, alo, wqhi, wqlo, qkv, N1, K);
    }
    // Prepass: extract/split Q,K and transposed V
    {
        int nthr = BH * TSEQ * 16; // float4 units
        qk_split_kernel<<<nthr / 256, 256>>>(qkv, qhi, qlo, khi, klo);
        dim3 gv(TSEQ / 32, HDIM / 32, BH);
        v_tsplit_kernel<<<gv, dim3(32, 8)>>>(qkv, vthi, vtlo);
    }
    // Stage 2: HMMA flash attention -> y (directly as bf16 hi/lo into ahi/alo)
    {
        dim3 grid(TSEQ / AQ, BH);
        attn_hmma_kernel<<<grid, 256, ATTN_SMEM_B>>>(qhi, qlo, khi, klo, vthi, vtlo,
                                                     (uint32_t*)ahi, (uint32_t*)alo);
    }
    // Stage 3: out = y @ w_proj  (HMMA)
    {
        dim3 grid(N2 / 128, M / 128);
        gemm_hmma3_kernel<<<grid, 256, GEMM_SMEM>>>(ahi, alo, wphi, wplo, out, N2, K);
    }
}